// round 1
// baseline (speedup 1.0000x reference)
#include <cuda_runtime.h>
#include <cstdint>

namespace {

constexpr int NB    = 4;       // N_BLOCKS
constexpr int DIN_  = 4000;
constexpr int DE_   = 128;
constexpr int DB_   = 8;
constexpr int KDIM  = DIN_ + DE_ + DB_;   // 4136
constexpr int MD    = 512;                // DLAT
constexpr int NROW  = 4096;
constexpr float ALPHA = 0.3f;

constexpr int BM  = 128;
constexpr int BN  = 128;
constexpr int BK  = 8;
constexpr int AST = BM + 4;   // padded stride: 132 floats, keeps 16B alignment, kills store conflicts

__global__ __launch_bounds__(256, 2)
void fused_inputblock_kernel(const float*    __restrict__ x,
                             const uint32_t* __restrict__ mask,      // raw bits: nonzero == true
                             const float*    __restrict__ embed,
                             const float*    __restrict__ batches,
                             const float*    __restrict__ mean_vals,
                             const float*    __restrict__ W,
                             const float*    __restrict__ bias,
                             float*          __restrict__ out)
{
    __shared__ float As[BK][AST];   // A stored transposed: As[k][m]
    __shared__ float Bs[BK][BN];

    const int b  = blockIdx.z;          // which of the 4 blocks
    const int rB = blockIdx.y * BM;     // row (N) base
    const int cB = blockIdx.x * BN;     // col (DLAT) base
    const int t  = threadIdx.x;
    const int tx = t & 15;              // 0..15 -> column group
    const int ty = t >> 4;              // 0..15 -> row group

    // A-tile global load mapping: thread t loads 4 consecutive k for one row
    const int arow = t >> 1;            // 0..127 local row
    const int akq  = (t & 1) << 2;      // 0 or 4 within the 8-wide k tile
    const int an   = rB + arow;         // global row

    // B-tile global load mapping: thread t loads 4 consecutive cols of one k row
    const int bkr = t >> 5;             // 0..7 k within tile
    const int bcc = (t & 31) << 2;      // 0..124 col within tile

    const float* Wb = W + (size_t)b * KDIM * MD + cB;

    float acc[8][8];
#pragma unroll
    for (int i = 0; i < 8; i++)
#pragma unroll
        for (int j = 0; j < 8; j++) acc[i][j] = 0.f;

    constexpr int NIT = KDIM / BK;      // 517, exact (no remainder)
    for (int kt = 0; kt < NIT; kt++) {
        const int k0 = kt * BK;

        // ---- fused A construction (masked-center | embed | batches) ----
        float a0, a1, a2, a3;
        if (k0 < DIN_) {
            const int gk = k0 + akq;
            const size_t xi = (size_t)an * (NB * DIN_) + b * DIN_ + gk;
            const float4 xv = *reinterpret_cast<const float4*>(x + xi);
            const uint4  mv = *reinterpret_cast<const uint4*>(mask + xi);
            const float4 mu = *reinterpret_cast<const float4*>(mean_vals + b * DIN_ + gk);
            a0 = mv.x ? xv.x - mu.x : 0.f;
            a1 = mv.y ? xv.y - mu.y : 0.f;
            a2 = mv.z ? xv.z - mu.z : 0.f;
            a3 = mv.w ? xv.w - mu.w : 0.f;
        } else if (k0 < DIN_ + DE_) {
            const int e = k0 - DIN_ + akq;
            const float4 ev = *reinterpret_cast<const float4*>(
                embed + (size_t)an * (NB * DE_) + b * DE_ + e);
            a0 = ev.x; a1 = ev.y; a2 = ev.z; a3 = ev.w;
        } else {
            const float4 bv = *reinterpret_cast<const float4*>(
                batches + (size_t)an * DB_ + akq);
            a0 = bv.x; a1 = bv.y; a2 = bv.z; a3 = bv.w;
        }

        const float4 wv = *reinterpret_cast<const float4*>(
            Wb + (size_t)(k0 + bkr) * MD + bcc);

        __syncthreads();   // previous iteration's compute done reading smem
        As[akq + 0][arow] = a0;
        As[akq + 1][arow] = a1;
        As[akq + 2][arow] = a2;
        As[akq + 3][arow] = a3;
        *reinterpret_cast<float4*>(&Bs[bkr][bcc]) = wv;
        __syncthreads();   // tiles ready

#pragma unroll
        for (int kk = 0; kk < BK; kk++) {
            const float4 A0 = *reinterpret_cast<const float4*>(&As[kk][ty * 4]);
            const float4 A1 = *reinterpret_cast<const float4*>(&As[kk][64 + ty * 4]);
            const float4 B0 = *reinterpret_cast<const float4*>(&Bs[kk][tx * 4]);
            const float4 B1 = *reinterpret_cast<const float4*>(&Bs[kk][64 + tx * 4]);
            const float av[8] = {A0.x, A0.y, A0.z, A0.w, A1.x, A1.y, A1.z, A1.w};
            const float bv[8] = {B0.x, B0.y, B0.z, B0.w, B1.x, B1.y, B1.z, B1.w};
#pragma unroll
            for (int i = 0; i < 8; i++)
#pragma unroll
                for (int j = 0; j < 8; j++)
                    acc[i][j] = fmaf(av[i], bv[j], acc[i][j]);
        }
    }

    // ---- epilogue: bias + LeakyReLU(0.3), vectorized stores ----
    const float* bb = bias + b * MD + cB;
    float bcol[8];
#pragma unroll
    for (int j = 0; j < 8; j++) {
        const int cj = (j < 4) ? (tx * 4 + j) : (64 + tx * 4 + (j - 4));
        bcol[j] = bb[cj];
    }

#pragma unroll
    for (int i = 0; i < 8; i++) {
        const int rloc = (i < 4) ? (ty * 4 + i) : (64 + ty * 4 + (i - 4));
        const int n = rB + rloc;
        float* orow = out + (size_t)n * (NB * MD) + b * MD + cB;
#pragma unroll
        for (int g = 0; g < 2; g++) {
            float v[4];
#pragma unroll
            for (int q = 0; q < 4; q++) {
                float h = acc[i][g * 4 + q] + bcol[g * 4 + q];
                v[q] = (h >= 0.f) ? h : ALPHA * h;
            }
            float4 o = make_float4(v[0], v[1], v[2], v[3]);
            const int c0 = g * 64 + tx * 4;
            *reinterpret_cast<float4*>(orow + c0) = o;
        }
    }
}

} // anonymous namespace

extern "C" void kernel_launch(void* const* d_in, const int* in_sizes, int n_in,
                              void* d_out, int out_size)
{
    const float*    x        = (const float*)d_in[0];
    const uint32_t* mask     = (const uint32_t*)d_in[1];
    const float*    embed    = (const float*)d_in[2];
    const float*    batches  = (const float*)d_in[3];
    const float*    mean     = (const float*)d_in[4];
    const float*    W        = (const float*)d_in[5];
    const float*    bias     = (const float*)d_in[6];
    float*          out      = (float*)d_out;

    dim3 grid(MD / BN, NROW / BM, NB);   // (4, 32, 4)
    fused_inputblock_kernel<<<grid, 256>>>(x, mask, embed, batches, mean, W, bias, out);
}

// round 3
// speedup vs baseline: 1.7693x; 1.7693x over previous
#include <cuda_runtime.h>
#include <cstdint>

namespace {

constexpr int NB = 4, DIN = 4000, DE = 128, DB = 8;
constexpr int KD = DIN + DE + DB;   // 4136
constexpr int MD = 512;
constexpr float ALPHA = 0.3f;
constexpr int NSLAB = 130;          // 129 x 32K + 1 x 8K
constexpr int BUF_BYTES = 32768;    // 16KB A-frags + 16KB B-frags
constexpr int SMEM_BYTES = 2 * BUF_BYTES;

__device__ __forceinline__ uint32_t tf32r(float f) {
    uint32_t u;
    asm("cvt.rna.tf32.f32 %0, %1;" : "=r"(u) : "f"(f));
    return u;
}
__device__ __forceinline__ uint32_t smem_u32(const void* p) {
    uint32_t a;
    asm("{ .reg .u64 t; cvta.to.shared.u64 t, %1; cvt.u32.u64 %0, t; }" : "=r"(a) : "l"(p));
    return a;
}
__device__ __forceinline__ void sts32(uint32_t a, uint32_t v) {
    asm volatile("st.shared.b32 [%0], %1;" :: "r"(a), "r"(v) : "memory");
}
__device__ __forceinline__ void lds128(uint32_t a, uint32_t* r) {
    asm volatile("ld.shared.v4.b32 {%0,%1,%2,%3}, [%4];"
                 : "=r"(r[0]), "=r"(r[1]), "=r"(r[2]), "=r"(r[3]) : "r"(a));
}
__device__ __forceinline__ void mma8(float* d, const uint32_t* a, uint32_t b0, uint32_t b1) {
    asm volatile(
        "mma.sync.aligned.m16n8k8.row.col.f32.tf32.tf32.f32 "
        "{%0,%1,%2,%3}, {%4,%5,%6,%7}, {%8,%9}, {%0,%1,%2,%3};"
        : "+f"(d[0]), "+f"(d[1]), "+f"(d[2]), "+f"(d[3])
        : "r"(a[0]), "r"(a[1]), "r"(a[2]), "r"(a[3]), "r"(b0), "r"(b1));
}

// A fragment addr: [ks 0..3][mf 0..7][slot 0..31] x 16B ; slot = lane ^ ks
__device__ __forceinline__ uint32_t a_addr(uint32_t base, int ks, int mf, int slot) {
    return base + (uint32_t)(((ks * 8 + mf) * 32 + slot) << 4);
}
// B fragment addr: [ks 0..3][npair 0..7][slot 0..31] x 16B ; slot = lane ^ npair
__device__ __forceinline__ uint32_t b_addr(uint32_t base, int ks, int np, int slot) {
    return base + 16384u + (uint32_t)(((ks * 8 + np) * 32 + slot) << 4);
}

struct Stage {
    uint32_t va[16];   // A values (tf32 bits)
    uint32_t wv[16];   // B values (tf32 bits)
};

__global__ void __launch_bounds__(256, 1)
ib_mma_kernel(const float*    __restrict__ x,
              const uint32_t* __restrict__ mask,
              const float*    __restrict__ embed,
              const float*    __restrict__ batches,
              const float*    __restrict__ mean,
              const float*    __restrict__ W,
              const float*    __restrict__ bias,
              float*          __restrict__ out)
{
    extern __shared__ char smem[];
    const uint32_t sb = smem_u32(smem);
    const int t    = threadIdx.x;
    const int lane = t & 31;
    const int wid  = t >> 5;
    const int wm   = wid & 3;        // warp row 0..3  (32 rows each)
    const int wn   = wid >> 2;       // warp col 0..1  (64 cols each)
    const int b    = blockIdx.z;
    const int rB   = blockIdx.y * 128;
    const int cB   = blockIdx.x * 128;

    const float* Wb = W + (size_t)b * KD * MD + cB;

    float acc[2][8][4];
#pragma unroll
    for (int m = 0; m < 2; m++)
#pragma unroll
        for (int n = 0; n < 8; n++)
#pragma unroll
            for (int q = 0; q < 4; q++) acc[m][n][q] = 0.f;

    Stage st;

    // ---------------- staging: gmem -> regs (fused A construction) ----------------
    auto stage_load = [&](int s) {
        const int k0 = s * 32;
        if (s < 125) {                                   // x region
#pragma unroll
            for (int p = 0; p < 4; p++) {
                const int idx = p * 256 + t;
                const int row = idx >> 3, q = idx & 7;
                const size_t gx = (size_t)(rB + row) * (NB * DIN) + (size_t)b * DIN + k0 + q * 4;
                const float4 xv = *reinterpret_cast<const float4*>(x + gx);
                const uint4  mv = *reinterpret_cast<const uint4*>(mask + gx);
                const float4 mu = *reinterpret_cast<const float4*>(mean + b * DIN + k0 + q * 4);
                st.va[p * 4 + 0] = mv.x ? tf32r(xv.x - mu.x) : 0u;
                st.va[p * 4 + 1] = mv.y ? tf32r(xv.y - mu.y) : 0u;
                st.va[p * 4 + 2] = mv.z ? tf32r(xv.z - mu.z) : 0u;
                st.va[p * 4 + 3] = mv.w ? tf32r(xv.w - mu.w) : 0u;
            }
        } else if (s < 129) {                            // embed region
            const int e0 = k0 - DIN;
#pragma unroll
            for (int p = 0; p < 4; p++) {
                const int idx = p * 256 + t;
                const int row = idx >> 3, q = idx & 7;
                const float4 ev = *reinterpret_cast<const float4*>(
                    embed + (size_t)(rB + row) * (NB * DE) + b * DE + e0 + q * 4);
                st.va[p * 4 + 0] = tf32r(ev.x);
                st.va[p * 4 + 1] = tf32r(ev.y);
                st.va[p * 4 + 2] = tf32r(ev.z);
                st.va[p * 4 + 3] = tf32r(ev.w);
            }
        } else {                                         // batches tail (8K)
            const int row = t >> 1, q = t & 1;
            const float4 bv = *reinterpret_cast<const float4*>(
                batches + (size_t)(rB + row) * DB + q * 4);
            st.va[0] = tf32r(bv.x); st.va[1] = tf32r(bv.y);
            st.va[2] = tf32r(bv.z); st.va[3] = tf32r(bv.w);
        }
        // B = W rows k0.. , cols cB..cB+127
        if (s < 129) {
#pragma unroll
            for (int p = 0; p < 4; p++) {
                const int idx = p * 256 + t;
                const int krow = idx >> 5, n0 = (idx & 31) * 4;
                const float4 wv4 = *reinterpret_cast<const float4*>(
                    Wb + (size_t)(k0 + krow) * MD + n0);
                st.wv[p * 4 + 0] = tf32r(wv4.x);
                st.wv[p * 4 + 1] = tf32r(wv4.y);
                st.wv[p * 4 + 2] = tf32r(wv4.z);
                st.wv[p * 4 + 3] = tf32r(wv4.w);
            }
        } else {
            const int krow = t >> 5, n0 = (t & 31) * 4;  // 8 x 128
            const float4 wv4 = *reinterpret_cast<const float4*>(
                Wb + (size_t)(k0 + krow) * MD + n0);
            st.wv[0] = tf32r(wv4.x); st.wv[1] = tf32r(wv4.y);
            st.wv[2] = tf32r(wv4.z); st.wv[3] = tf32r(wv4.w);
        }
    };

    // ---------------- staging: regs -> smem (fragment layout) ----------------
    auto stage_store = [&](int s, uint32_t base) {
        if (s < 129) {
#pragma unroll
            for (int p = 0; p < 4; p++) {
                const int idx = p * 256 + t;
                const int row = idx >> 3, q = idx & 7;
                const int ks = q >> 1, mf = row >> 4, rin = row & 15;
                const int g = rin & 7, reg = (rin >> 3) + 2 * (q & 1);
#pragma unroll
                for (int i = 0; i < 4; i++) {
                    const int slot = (g * 4 + i) ^ ks;
                    sts32(a_addr(base, ks, mf, slot) + reg * 4, st.va[p * 4 + i]);
                }
            }
#pragma unroll
            for (int p = 0; p < 4; p++) {
                const int idx = p * 256 + t;
                const int krow = idx >> 5, n0 = (idx & 31) * 4;
                const int ks = krow >> 3, tk = krow & 3, kh = (krow >> 2) & 1;
#pragma unroll
                for (int i = 0; i < 4; i++) {
                    const int n = n0 + i, g = n & 7, nf = n >> 3, np = nf >> 1;
                    const int reg = (nf & 1) * 2 + kh;
                    const int slot = (g * 4 + tk) ^ np;
                    sts32(b_addr(base, ks, np, slot) + reg * 4, st.wv[p * 4 + i]);
                }
            }
        } else {
            // A tail: row = t>>1, khalf = t&1, cols khalf*4 + i  (ks = 0)
            const int row = t >> 1, q = t & 1;
            const int mf = row >> 4, rin = row & 15;
            const int g = rin & 7, reg = (rin >> 3) + 2 * q;
#pragma unroll
            for (int i = 0; i < 4; i++)
                sts32(a_addr(base, 0, mf, g * 4 + i) + reg * 4, st.va[i]);
            // B tail: krow = t>>5 (0..7), ks = 0
            const int krow = t >> 5, n0 = (t & 31) * 4;
            const int tk = krow & 3, kh = (krow >> 2) & 1;
#pragma unroll
            for (int i = 0; i < 4; i++) {
                const int n = n0 + i, g = n & 7, nf = n >> 3, np = nf >> 1;
                const int reg = (nf & 1) * 2 + kh;
                const int slot = (g * 4 + tk) ^ np;
                sts32(b_addr(base, 0, np, slot) + reg * 4, st.wv[i]);
            }
        }
    };

    // ---------------- consumer: LDS.128 fragments + HMMA ----------------
    auto consume = [&](uint32_t base, int nks) {
        for (int ks = 0; ks < nks; ks++) {
            uint32_t afr[2][4], bfr[4][4];
#pragma unroll
            for (int m = 0; m < 2; m++)
                lds128(a_addr(base, ks, wm * 2 + m, lane ^ ks), afr[m]);
#pragma unroll
            for (int pp = 0; pp < 4; pp++) {
                const int np = wn * 4 + pp;
                lds128(b_addr(base, ks, np, lane ^ np), bfr[pp]);
            }
#pragma unroll
            for (int m = 0; m < 2; m++)
#pragma unroll
                for (int pp = 0; pp < 4; pp++) {
                    mma8(acc[m][2 * pp],     afr[m], bfr[pp][0], bfr[pp][1]);
                    mma8(acc[m][2 * pp + 1], afr[m], bfr[pp][2], bfr[pp][3]);
                }
        }
    };

    // ---------------- pipelined mainloop ----------------
    stage_load(0);
    stage_store(0, sb);
    __syncthreads();

    for (int s = 0; s < NSLAB; s++) {
        const uint32_t cur = sb + (uint32_t)((s & 1) * BUF_BYTES);
        if (s + 1 < NSLAB) stage_load(s + 1);
        consume(cur, (s == 129) ? 1 : 4);
        if (s + 1 < NSLAB) stage_store(s + 1, sb + (uint32_t)(((s + 1) & 1) * BUF_BYTES));
        __syncthreads();
    }

    // ---------------- epilogue: bias + LeakyReLU, direct gmem stores ----------------
    const int g  = lane >> 2;
    const int tq = lane & 3;
#pragma unroll
    for (int m = 0; m < 2; m++) {
        const int r0 = rB + wm * 32 + m * 16 + g;
#pragma unroll
        for (int nf = 0; nf < 8; nf++) {
            const int col = cB + wn * 64 + nf * 8 + tq * 2;
            const float2 bv = *reinterpret_cast<const float2*>(bias + b * MD + col);
            float v0 = acc[m][nf][0] + bv.x;
            float v1 = acc[m][nf][1] + bv.y;
            float v2 = acc[m][nf][2] + bv.x;
            float v3 = acc[m][nf][3] + bv.y;
            v0 = (v0 >= 0.f) ? v0 : ALPHA * v0;
            v1 = (v1 >= 0.f) ? v1 : ALPHA * v1;
            v2 = (v2 >= 0.f) ? v2 : ALPHA * v2;
            v3 = (v3 >= 0.f) ? v3 : ALPHA * v3;
            *reinterpret_cast<float2*>(out + (size_t)r0 * (NB * MD) + b * MD + col)
                = make_float2(v0, v1);
            *reinterpret_cast<float2*>(out + (size_t)(r0 + 8) * (NB * MD) + b * MD + col)
                = make_float2(v2, v3);
        }
    }
}

} // namespace

extern "C" void kernel_launch(void* const* d_in, const int* in_sizes, int n_in,
                              void* d_out, int out_size)
{
    const float*    x       = (const float*)d_in[0];
    const uint32_t* mask    = (const uint32_t*)d_in[1];
    const float*    embed   = (const float*)d_in[2];
    const float*    batches = (const float*)d_in[3];
    const float*    mean    = (const float*)d_in[4];
    const float*    W       = (const float*)d_in[5];
    const float*    bias    = (const float*)d_in[6];
    float*          out     = (float*)d_out;

    cudaFuncSetAttribute(ib_mma_kernel, cudaFuncAttributeMaxDynamicSharedMemorySize, SMEM_BYTES);
    dim3 grid(MD / 128, 4096 / 128, NB);   // (4, 32, 4)
    ib_mma_kernel<<<grid, 256, SMEM_BYTES>>>(x, mask, embed, batches, mean, W, bias, out);
}

// round 4
// speedup vs baseline: 2.3677x; 1.3382x over previous
#include <cuda_runtime.h>
#include <cstdint>

namespace {

constexpr int NB = 4, DIN = 4000, DE = 128, DB = 8;
constexpr int KD = DIN + DE + DB;   // 4136
constexpr int MD = 512;
constexpr float ALPHA = 0.3f;
constexpr int NSLAB = 130;          // 129 x 32K + 1 x 8K
constexpr int BUF_BYTES = 32768;    // 16KB A-frags + 16KB B-frags
constexpr int SMEM_BYTES = 2 * BUF_BYTES;

__device__ __forceinline__ uint32_t tf32r(float f) {
    uint32_t u;
    asm("cvt.rna.tf32.f32 %0, %1;" : "=r"(u) : "f"(f));
    return u;
}
__device__ __forceinline__ uint32_t smem_u32(const void* p) {
    uint32_t a;
    asm("{ .reg .u64 t; cvta.to.shared.u64 t, %1; cvt.u32.u64 %0, t; }" : "=r"(a) : "l"(p));
    return a;
}
__device__ __forceinline__ void sts32(uint32_t a, uint32_t v) {
    asm volatile("st.shared.b32 [%0], %1;" :: "r"(a), "r"(v) : "memory");
}
__device__ __forceinline__ void lds128(uint32_t a, uint32_t* r) {
    asm volatile("ld.shared.v4.b32 {%0,%1,%2,%3}, [%4];"
                 : "=r"(r[0]), "=r"(r[1]), "=r"(r[2]), "=r"(r[3]) : "r"(a));
}
__device__ __forceinline__ void mma8(float* d, const uint32_t* a, uint32_t b0, uint32_t b1) {
    asm volatile(
        "mma.sync.aligned.m16n8k8.row.col.f32.tf32.tf32.f32 "
        "{%0,%1,%2,%3}, {%4,%5,%6,%7}, {%8,%9}, {%0,%1,%2,%3};"
        : "+f"(d[0]), "+f"(d[1]), "+f"(d[2]), "+f"(d[3])
        : "r"(a[0]), "r"(a[1]), "r"(a[2]), "r"(a[3]), "r"(b0), "r"(b1));
}

// A fragment addr: [ks 0..3][mf 0..7][slot 0..31] x 16B ; slot = lane ^ ks
__device__ __forceinline__ uint32_t a_addr(uint32_t base, int ks, int mf, int slot) {
    return base + (uint32_t)(((ks * 8 + mf) * 32 + slot) << 4);
}
// B fragment addr: [ks 0..3][npair 0..7][slot 0..31] x 16B ; slot = lane ^ npair
__device__ __forceinline__ uint32_t b_addr(uint32_t base, int ks, int np, int slot) {
    return base + 16384u + (uint32_t)(((ks * 8 + np) * 32 + slot) << 4);
}

__global__ void __launch_bounds__(256, 2)
ib_mma_kernel(const float*    __restrict__ x,
              const uint32_t* __restrict__ mask,
              const float*    __restrict__ embed,
              const float*    __restrict__ batches,
              const float*    __restrict__ mean,
              const float*    __restrict__ W,
              const float*    __restrict__ bias,
              float*          __restrict__ out)
{
    extern __shared__ char smem[];
    const uint32_t sb = smem_u32(smem);
    const int t    = threadIdx.x;
    const int lane = t & 31;
    const int wid  = t >> 5;
    const int wm   = wid & 3;        // warp row 0..3  (32 rows each)
    const int wn   = wid >> 2;       // warp col 0..1  (64 cols each)
    const int b    = blockIdx.z;
    const int rB   = blockIdx.y * 128;
    const int cB   = blockIdx.x * 128;

    const float* Wb = W + (size_t)b * KD * MD + cB;

    float acc[2][8][4];
#pragma unroll
    for (int m = 0; m < 2; m++)
#pragma unroll
        for (int n = 0; n < 8; n++)
#pragma unroll
            for (int q = 0; q < 4; q++) acc[m][n][q] = 0.f;

    uint32_t v8[8];   // staging half (A or W), reused

    // -------- A staging, half h covers passes 2h, 2h+1 --------
    auto loadA_h = [&](int s, int h) {
        const int k0 = s * 32;
        if (s < 125) {
#pragma unroll
            for (int pp = 0; pp < 2; pp++) {
                const int idx = (2 * h + pp) * 256 + t;
                const int row = idx >> 3, q = idx & 7;
                const size_t gx = (size_t)(rB + row) * (NB * DIN) + (size_t)b * DIN + k0 + q * 4;
                const float4 xv = *reinterpret_cast<const float4*>(x + gx);
                const uint4  mv = *reinterpret_cast<const uint4*>(mask + gx);
                const float4 mu = *reinterpret_cast<const float4*>(mean + b * DIN + k0 + q * 4);
                v8[pp * 4 + 0] = mv.x ? tf32r(xv.x - mu.x) : 0u;
                v8[pp * 4 + 1] = mv.y ? tf32r(xv.y - mu.y) : 0u;
                v8[pp * 4 + 2] = mv.z ? tf32r(xv.z - mu.z) : 0u;
                v8[pp * 4 + 3] = mv.w ? tf32r(xv.w - mu.w) : 0u;
            }
        } else if (s < 129) {
            const int e0 = k0 - DIN;
#pragma unroll
            for (int pp = 0; pp < 2; pp++) {
                const int idx = (2 * h + pp) * 256 + t;
                const int row = idx >> 3, q = idx & 7;
                const float4 ev = *reinterpret_cast<const float4*>(
                    embed + (size_t)(rB + row) * (NB * DE) + b * DE + e0 + q * 4);
                v8[pp * 4 + 0] = tf32r(ev.x);
                v8[pp * 4 + 1] = tf32r(ev.y);
                v8[pp * 4 + 2] = tf32r(ev.z);
                v8[pp * 4 + 3] = tf32r(ev.w);
            }
        } else if (h == 0) {                 // batches tail (8K), one pass
            const float4 bv = *reinterpret_cast<const float4*>(
                batches + (size_t)(rB + (t >> 1)) * DB + (t & 1) * 4);
            v8[0] = tf32r(bv.x); v8[1] = tf32r(bv.y);
            v8[2] = tf32r(bv.z); v8[3] = tf32r(bv.w);
        }
    };
    auto storeA_h = [&](int s, int h, uint32_t base) {
        if (s < 129) {
#pragma unroll
            for (int pp = 0; pp < 2; pp++) {
                const int idx = (2 * h + pp) * 256 + t;
                const int row = idx >> 3, q = idx & 7;
                const int ks = q >> 1, mf = row >> 4, rin = row & 15;
                const int g = rin & 7, reg = (rin >> 3) + 2 * (q & 1);
#pragma unroll
                for (int i = 0; i < 4; i++) {
                    const int slot = (g * 4 + i) ^ ks;
                    sts32(a_addr(base, ks, mf, slot) + reg * 4, v8[pp * 4 + i]);
                }
            }
        } else if (h == 0) {
            const int row = t >> 1, q = t & 1;
            const int mf = row >> 4, rin = row & 15;
            const int g = rin & 7, reg = (rin >> 3) + 2 * q;
#pragma unroll
            for (int i = 0; i < 4; i++)
                sts32(a_addr(base, 0, mf, g * 4 + i) + reg * 4, v8[i]);
        }
    };

    // -------- W staging, half h covers passes 2h, 2h+1 --------
    auto loadW_h = [&](int s, int h) {
        const int k0 = s * 32;
        if (s < 129) {
#pragma unroll
            for (int pp = 0; pp < 2; pp++) {
                const int idx = (2 * h + pp) * 256 + t;
                const int krow = idx >> 5, n0 = (idx & 31) * 4;
                const float4 wv4 = *reinterpret_cast<const float4*>(
                    Wb + (size_t)(k0 + krow) * MD + n0);
                v8[pp * 4 + 0] = tf32r(wv4.x);
                v8[pp * 4 + 1] = tf32r(wv4.y);
                v8[pp * 4 + 2] = tf32r(wv4.z);
                v8[pp * 4 + 3] = tf32r(wv4.w);
            }
        } else if (h == 0) {
            const float4 wv4 = *reinterpret_cast<const float4*>(
                Wb + (size_t)(k0 + (t >> 5)) * MD + (t & 31) * 4);
            v8[0] = tf32r(wv4.x); v8[1] = tf32r(wv4.y);
            v8[2] = tf32r(wv4.z); v8[3] = tf32r(wv4.w);
        }
    };
    auto storeW_h = [&](int s, int h, uint32_t base) {
        if (s < 129) {
#pragma unroll
            for (int pp = 0; pp < 2; pp++) {
                const int idx = (2 * h + pp) * 256 + t;
                const int krow = idx >> 5, n0 = (idx & 31) * 4;
                const int ks = krow >> 3, tk = krow & 3, kh = (krow >> 2) & 1;
#pragma unroll
                for (int i = 0; i < 4; i++) {
                    const int n = n0 + i, g = n & 7, nf = n >> 3, np = nf >> 1;
                    const int reg = (nf & 1) * 2 + kh;
                    const int slot = (g * 4 + tk) ^ np;
                    sts32(b_addr(base, ks, np, slot) + reg * 4, v8[pp * 4 + i]);
                }
            }
        } else if (h == 0) {
            const int krow = t >> 5, n0 = (t & 31) * 4;
            const int tk = krow & 3, kh = (krow >> 2) & 1;
#pragma unroll
            for (int i = 0; i < 4; i++) {
                const int n = n0 + i, g = n & 7, nf = n >> 3, np = nf >> 1;
                const int reg = (nf & 1) * 2 + kh;
                const int slot = (g * 4 + tk) ^ np;
                sts32(b_addr(base, 0, np, slot) + reg * 4, v8[i]);
            }
        }
    };

    // -------- consume one K8 step (compile-time unrolled MMA block) --------
    auto consume = [&](uint32_t base, int ks) {
        uint32_t afr[2][4], bfr[4][4];
#pragma unroll
        for (int m = 0; m < 2; m++)
            lds128(a_addr(base, ks, wm * 2 + m, lane ^ ks), afr[m]);
#pragma unroll
        for (int pp = 0; pp < 4; pp++) {
            const int np = wn * 4 + pp;
            lds128(b_addr(base, ks, np, lane ^ np), bfr[pp]);
        }
#pragma unroll
        for (int m = 0; m < 2; m++)
#pragma unroll
            for (int pp = 0; pp < 4; pp++) {
                mma8(acc[m][2 * pp],     afr[m], bfr[pp][0], bfr[pp][1]);
                mma8(acc[m][2 * pp + 1], afr[m], bfr[pp][2], bfr[pp][3]);
            }
    };

    // -------- prologue: stage slab 0 into buffer 0 --------
    loadA_h(0, 0); storeA_h(0, 0, sb);
    loadA_h(0, 1); storeA_h(0, 1, sb);
    loadW_h(0, 0); storeW_h(0, 0, sb);
    loadW_h(0, 1); storeW_h(0, 1, sb);
    __syncthreads();

    // -------- mainloop: 129 full slabs, prefetch s+1 interleaved with MMA --------
    for (int s = 0; s < 129; s++) {
        const uint32_t cur = sb + (uint32_t)((s & 1) * BUF_BYTES);
        const uint32_t nxt = sb + (uint32_t)(((s + 1) & 1) * BUF_BYTES);
        loadA_h(s + 1, 0);
        consume(cur, 0);
        storeA_h(s + 1, 0, nxt);
        loadA_h(s + 1, 1);
        consume(cur, 1);
        storeA_h(s + 1, 1, nxt);
        loadW_h(s + 1, 0);
        consume(cur, 2);
        storeW_h(s + 1, 0, nxt);
        loadW_h(s + 1, 1);
        consume(cur, 3);
        storeW_h(s + 1, 1, nxt);
        __syncthreads();
    }

    // -------- tail slab (s=129, 8K, buffer 1) --------
    consume(sb + BUF_BYTES, 0);

    // -------- epilogue: bias + LeakyReLU, direct gmem stores --------
    const int g  = lane >> 2;
    const int tq = lane & 3;
#pragma unroll
    for (int m = 0; m < 2; m++) {
        const int r0 = rB + wm * 32 + m * 16 + g;
#pragma unroll
        for (int nf = 0; nf < 8; nf++) {
            const int col = cB + wn * 64 + nf * 8 + tq * 2;
            const float2 bv = *reinterpret_cast<const float2*>(bias + b * MD + col);
            float v0 = acc[m][nf][0] + bv.x;
            float v1 = acc[m][nf][1] + bv.y;
            float v2 = acc[m][nf][2] + bv.x;
            float v3 = acc[m][nf][3] + bv.y;
            v0 = (v0 >= 0.f) ? v0 : ALPHA * v0;
            v1 = (v1 >= 0.f) ? v1 : ALPHA * v1;
            v2 = (v2 >= 0.f) ? v2 : ALPHA * v2;
            v3 = (v3 >= 0.f) ? v3 : ALPHA * v3;
            *reinterpret_cast<float2*>(out + (size_t)r0 * (NB * MD) + b * MD + col)
                = make_float2(v0, v1);
            *reinterpret_cast<float2*>(out + (size_t)(r0 + 8) * (NB * MD) + b * MD + col)
                = make_float2(v2, v3);
        }
    }
}

} // namespace

extern "C" void kernel_launch(void* const* d_in, const int* in_sizes, int n_in,
                              void* d_out, int out_size)
{
    const float*    x       = (const float*)d_in[0];
    const uint32_t* mask    = (const uint32_t*)d_in[1];
    const float*    embed   = (const float*)d_in[2];
    const float*    batches = (const float*)d_in[3];
    const float*    mean    = (const float*)d_in[4];
    const float*    W       = (const float*)d_in[5];
    const float*    bias    = (const float*)d_in[6];
    float*          out     = (float*)d_out;

    cudaFuncSetAttribute(ib_mma_kernel, cudaFuncAttributeMaxDynamicSharedMemorySize, SMEM_BYTES);
    dim3 grid(MD / 128, 4096 / 128, NB);   // (4, 32, 4)
    ib_mma_kernel<<<grid, 256, SMEM_BYTES>>>(x, mask, embed, batches, mean, W, bias, out);
}

// round 5
// speedup vs baseline: 4.1079x; 1.7350x over previous
#include <cuda_runtime.h>
#include <cstdint>

namespace {

constexpr int NB = 4, DIN = 4000, DE = 128, DB = 8;
constexpr int KD = DIN + DE + DB;   // 4136
constexpr int MD = 512;
constexpr float ALPHA = 0.3f;
constexpr int NSLAB = 130;          // 129 x 32K + 1 x 8K(zero-padded to 32)
constexpr int SLAB_BYTES = 16384;   // one fragment image (A or B) per slab per tile
constexpr int BUF_BYTES  = 2 * SLAB_BYTES;      // A + B
constexpr int SMEM_MAIN  = 3 * BUF_BYTES;       // triple buffer = 96KB

// fragment-image scratch (written by prep kernels, read via cp.async)
__device__ __align__(16) uint8_t g_Afrag[(size_t)NB * 32 * NSLAB * SLAB_BYTES]; // 272.6MB
__device__ __align__(16) uint8_t g_Wfrag[(size_t)NB * 4  * NSLAB * SLAB_BYTES]; // 34MB

__device__ __forceinline__ uint32_t tf32r(float f) {
    uint32_t u;
    asm("cvt.rna.tf32.f32 %0, %1;" : "=r"(u) : "f"(f));
    return u;
}
__device__ __forceinline__ uint32_t smem_u32(const void* p) {
    uint32_t a;
    asm("{ .reg .u64 t; cvta.to.shared.u64 t, %1; cvt.u32.u64 %0, t; }" : "=r"(a) : "l"(p));
    return a;
}
__device__ __forceinline__ void sts32(uint32_t a, uint32_t v) {
    asm volatile("st.shared.b32 [%0], %1;" :: "r"(a), "r"(v) : "memory");
}
__device__ __forceinline__ void lds128(uint32_t a, uint32_t* r) {
    asm volatile("ld.shared.v4.b32 {%0,%1,%2,%3}, [%4];"
                 : "=r"(r[0]), "=r"(r[1]), "=r"(r[2]), "=r"(r[3]) : "r"(a));
}
__device__ __forceinline__ void mma8(float* d, const uint32_t* a, uint32_t b0, uint32_t b1) {
    asm volatile(
        "mma.sync.aligned.m16n8k8.row.col.f32.tf32.tf32.f32 "
        "{%0,%1,%2,%3}, {%4,%5,%6,%7}, {%8,%9}, {%0,%1,%2,%3};"
        : "+f"(d[0]), "+f"(d[1]), "+f"(d[2]), "+f"(d[3])
        : "r"(a[0]), "r"(a[1]), "r"(a[2]), "r"(a[3]), "r"(b0), "r"(b1));
}
__device__ __forceinline__ void cp16(uint32_t saddr, const void* gaddr) {
    asm volatile("cp.async.cg.shared.global [%0], [%1], 16;"
                 :: "r"(saddr), "l"(gaddr) : "memory");
}
#define CP_COMMIT() asm volatile("cp.async.commit_group;" ::: "memory")
#define CP_WAIT1()  asm volatile("cp.async.wait_group 1;" ::: "memory")

// fragment offsets within one 16KB slab image
__device__ __forceinline__ uint32_t fr_off(int ks, int f, int slot) {
    return (uint32_t)(((ks * 8 + f) * 32 + slot) << 4);
}

// ======================= prep A: x|embed|batches -> tf32 fragment image =======================
__global__ void __launch_bounds__(256)
prep_a(const float* __restrict__ x, const uint32_t* __restrict__ mask,
       const float* __restrict__ embed, const float* __restrict__ batches,
       const float* __restrict__ mean)
{
    __shared__ uint32_t sf[4096];
    const int s  = blockIdx.x;
    const int rt = blockIdx.y;
    const int b  = blockIdx.z;
    const int rB = rt * 128;
    const int t  = threadIdx.x;
    const uint32_t base = smem_u32(sf);
    const int k0 = s * 32;

    if (s == 129) {                       // zero-pad tail (ks 1..3)
        for (int i = t; i < 4096; i += 256) sf[i] = 0;
        __syncthreads();
    }

    if (s < 129) {
#pragma unroll 1
        for (int p = 0; p < 4; p++) {
            const int idx = p * 256 + t;
            const int row = idx >> 3, q = idx & 7;
            uint32_t v[4];
            if (s < 125) {
                const size_t gx = (size_t)(rB + row) * (NB * DIN) + (size_t)b * DIN + k0 + q * 4;
                const float4 xv = *reinterpret_cast<const float4*>(x + gx);
                const uint4  mv = *reinterpret_cast<const uint4*>(mask + gx);
                const float4 mu = *reinterpret_cast<const float4*>(mean + b * DIN + k0 + q * 4);
                v[0] = mv.x ? tf32r(xv.x - mu.x) : 0u;
                v[1] = mv.y ? tf32r(xv.y - mu.y) : 0u;
                v[2] = mv.z ? tf32r(xv.z - mu.z) : 0u;
                v[3] = mv.w ? tf32r(xv.w - mu.w) : 0u;
            } else {
                const float4 ev = *reinterpret_cast<const float4*>(
                    embed + (size_t)(rB + row) * (NB * DE) + b * DE + (k0 - DIN) + q * 4);
                v[0] = tf32r(ev.x); v[1] = tf32r(ev.y);
                v[2] = tf32r(ev.z); v[3] = tf32r(ev.w);
            }
            const int ks = q >> 1, mf = row >> 4, rin = row & 15;
            const int g = rin & 7, reg = (rin >> 3) + 2 * (q & 1);
#pragma unroll
            for (int i = 0; i < 4; i++)
                sts32(base + fr_off(ks, mf, (g * 4 + i) ^ ks) + reg * 4, v[i]);
        }
    } else {                              // batches tail: ks=0 only
        const int row = t >> 1, q = t & 1;
        const float4 bv = *reinterpret_cast<const float4*>(
            batches + (size_t)(rB + row) * DB + q * 4);
        const uint32_t v[4] = {tf32r(bv.x), tf32r(bv.y), tf32r(bv.z), tf32r(bv.w)};
        const int mf = row >> 4, rin = row & 15;
        const int g = rin & 7, reg = (rin >> 3) + 2 * q;
#pragma unroll
        for (int i = 0; i < 4; i++)
            sts32(base + fr_off(0, mf, g * 4 + i) + reg * 4, v[i]);
    }
    __syncthreads();

    uint4* dst = reinterpret_cast<uint4*>(
        g_Afrag + ((size_t)(b * 32 + rt) * NSLAB + s) * SLAB_BYTES);
    const uint4* src = reinterpret_cast<const uint4*>(sf);
#pragma unroll
    for (int i = 0; i < 4; i++) dst[i * 256 + t] = src[i * 256 + t];
}

// ======================= prep W: W -> tf32 fragment image =======================
__global__ void __launch_bounds__(256)
prep_w(const float* __restrict__ W)
{
    __shared__ uint32_t sf[4096];
    const int s   = blockIdx.x;
    const int cbi = blockIdx.y;
    const int b   = blockIdx.z;
    const int t   = threadIdx.x;
    const uint32_t base = smem_u32(sf);
    const int k0 = s * 32;
    const float* Wb = W + (size_t)b * KD * MD + cbi * 128;

    if (s == 129) {
        for (int i = t; i < 4096; i += 256) sf[i] = 0;
        __syncthreads();
    }

    const int npass = (s == 129) ? 1 : 4;
#pragma unroll 1
    for (int p = 0; p < npass; p++) {
        const int idx = p * 256 + t;
        const int krow = (s == 129) ? (t >> 5) : (idx >> 5);
        const int n0   = (idx & 31) * 4;
        const float4 wv4 = *reinterpret_cast<const float4*>(
            Wb + (size_t)(k0 + krow) * MD + n0);
        const uint32_t v[4] = {tf32r(wv4.x), tf32r(wv4.y), tf32r(wv4.z), tf32r(wv4.w)};
        const int ks = krow >> 3, tk = krow & 3, kh = (krow >> 2) & 1;
#pragma unroll
        for (int i = 0; i < 4; i++) {
            const int n = n0 + i, g = n & 7, nf = n >> 3, np = nf >> 1;
            const int reg = (nf & 1) * 2 + kh;
            sts32(base + fr_off(ks, np, (g * 4 + tk) ^ np) + reg * 4, v[i]);
        }
    }
    __syncthreads();

    uint4* dst = reinterpret_cast<uint4*>(
        g_Wfrag + ((size_t)(b * 4 + cbi) * NSLAB + s) * SLAB_BYTES);
    const uint4* src = reinterpret_cast<const uint4*>(sf);
#pragma unroll
    for (int i = 0; i < 4; i++) dst[i * 256 + t] = src[i * 256 + t];
}

// ======================= main: cp.async pipeline + HMMA =======================
__global__ void __launch_bounds__(256, 2)
ib_main(const float* __restrict__ bias, float* __restrict__ out)
{
    extern __shared__ char smem[];
    const uint32_t sb = smem_u32(smem);
    const int t    = threadIdx.x;
    const int lane = t & 31;
    const int wid  = t >> 5;
    const int wm   = wid & 3;
    const int wn   = wid >> 2;
    const int cbi  = blockIdx.x;
    const int rt   = blockIdx.y;
    const int b    = blockIdx.z;
    const int rB   = rt * 128;
    const int cB   = cbi * 128;

    const uint8_t* gA = g_Afrag + (size_t)(b * 32 + rt) * NSLAB * SLAB_BYTES;
    const uint8_t* gW = g_Wfrag + (size_t)(b * 4 + cbi) * NSLAB * SLAB_BYTES;

    float acc[2][8][4];
#pragma unroll
    for (int m = 0; m < 2; m++)
#pragma unroll
        for (int n = 0; n < 8; n++)
#pragma unroll
            for (int q = 0; q < 4; q++) acc[m][n][q] = 0.f;

    auto cp_slab = [&](int s) {
        const uint32_t buf = sb + (uint32_t)((s % 3) * BUF_BYTES);
        const uint8_t* as = gA + (size_t)s * SLAB_BYTES;
        const uint8_t* ws = gW + (size_t)s * SLAB_BYTES;
#pragma unroll
        for (int i = 0; i < 4; i++) {
            const uint32_t off = (uint32_t)(i * 256 + t) * 16;
            cp16(buf + off, as + off);
            cp16(buf + SLAB_BYTES + off, ws + off);
        }
    };

    auto consume = [&](uint32_t buf, int ks) {
        uint32_t afr[2][4], bfr[4][4];
#pragma unroll
        for (int m = 0; m < 2; m++)
            lds128(buf + fr_off(ks, wm * 2 + m, lane ^ ks), afr[m]);
#pragma unroll
        for (int pp = 0; pp < 4; pp++) {
            const int np = wn * 4 + pp;
            lds128(buf + SLAB_BYTES + fr_off(ks, np, lane ^ np), bfr[pp]);
        }
#pragma unroll
        for (int m = 0; m < 2; m++)
#pragma unroll
            for (int pp = 0; pp < 4; pp++) {
                mma8(acc[m][2 * pp],     afr[m], bfr[pp][0], bfr[pp][1]);
                mma8(acc[m][2 * pp + 1], afr[m], bfr[pp][2], bfr[pp][3]);
            }
    };

    // prologue: prefetch slabs 0,1
    cp_slab(0); CP_COMMIT();
    cp_slab(1); CP_COMMIT();

    for (int s = 0; s < NSLAB; s++) {
        CP_WAIT1();               // slab s arrived (<=1 newer group pending)
        __syncthreads();          // all warps done with slab s-1, data visible
        if (s + 2 < NSLAB) cp_slab(s + 2);
        CP_COMMIT();              // exactly one group per iteration
        const uint32_t buf = sb + (uint32_t)((s % 3) * BUF_BYTES);
        consume(buf, 0);
        consume(buf, 1);
        consume(buf, 2);
        consume(buf, 3);
    }

    // -------- epilogue: bias + LeakyReLU --------
    const int g  = lane >> 2;
    const int tq = lane & 3;
#pragma unroll
    for (int m = 0; m < 2; m++) {
        const int r0 = rB + wm * 32 + m * 16 + g;
#pragma unroll
        for (int nf = 0; nf < 8; nf++) {
            const int col = cB + wn * 64 + nf * 8 + tq * 2;
            const float2 bv = *reinterpret_cast<const float2*>(bias + b * MD + col);
            float v0 = acc[m][nf][0] + bv.x;
            float v1 = acc[m][nf][1] + bv.y;
            float v2 = acc[m][nf][2] + bv.x;
            float v3 = acc[m][nf][3] + bv.y;
            v0 = (v0 >= 0.f) ? v0 : ALPHA * v0;
            v1 = (v1 >= 0.f) ? v1 : ALPHA * v1;
            v2 = (v2 >= 0.f) ? v2 : ALPHA * v2;
            v3 = (v3 >= 0.f) ? v3 : ALPHA * v3;
            *reinterpret_cast<float2*>(out + (size_t)r0 * (NB * MD) + b * MD + col)
                = make_float2(v0, v1);
            *reinterpret_cast<float2*>(out + (size_t)(r0 + 8) * (NB * MD) + b * MD + col)
                = make_float2(v2, v3);
        }
    }
}

} // namespace

extern "C" void kernel_launch(void* const* d_in, const int* in_sizes, int n_in,
                              void* d_out, int out_size)
{
    const float*    x       = (const float*)d_in[0];
    const uint32_t* mask    = (const uint32_t*)d_in[1];
    const float*    embed   = (const float*)d_in[2];
    const float*    batches = (const float*)d_in[3];
    const float*    mean    = (const float*)d_in[4];
    const float*    W       = (const float*)d_in[5];
    const float*    bias    = (const float*)d_in[6];
    float*          out     = (float*)d_out;

    prep_w<<<dim3(NSLAB, 4, NB), 256>>>(W);
    prep_a<<<dim3(NSLAB, 32, NB), 256>>>(x, mask, embed, batches, mean);

    cudaFuncSetAttribute(ib_main, cudaFuncAttributeMaxDynamicSharedMemorySize, SMEM_MAIN);
    ib_main<<<dim3(4, 32, NB), 256, SMEM_MAIN>>>(bias, out);
}

// round 6
// speedup vs baseline: 4.1478x; 1.0097x over previous
#include <cuda_runtime.h>
#include <cstdint>

namespace {

constexpr int NB = 4, DIN = 4000, DE = 128, DB = 8;
constexpr int KD = DIN + DE + DB;   // 4136
constexpr int MD = 512;
constexpr float ALPHA = 0.3f;
constexpr int NSLAB = 130;          // 129 x 32K + 1 x 8K(zero-padded to 32)
constexpr int SLAB_BYTES = 16384;   // one fragment image (A or B) per slab per tile
constexpr int BUF_BYTES  = 2 * SLAB_BYTES;      // A + B
constexpr int SMEM_MAIN  = 3 * BUF_BYTES;       // triple buffer = 96KB

// fragment-image scratch (written by prep kernels, read via cp.async)
__device__ __align__(16) uint8_t g_Afrag[(size_t)NB * 32 * NSLAB * SLAB_BYTES]; // 272.6MB
__device__ __align__(16) uint8_t g_Wfrag[(size_t)NB * 4  * NSLAB * SLAB_BYTES]; // 34MB

__device__ __forceinline__ uint32_t tf32r(float f) {
    uint32_t u;
    asm("cvt.rna.tf32.f32 %0, %1;" : "=r"(u) : "f"(f));
    return u;
}
__device__ __forceinline__ uint32_t smem_u32(const void* p) {
    uint32_t a;
    asm("{ .reg .u64 t; cvta.to.shared.u64 t, %1; cvt.u32.u64 %0, t; }" : "=r"(a) : "l"(p));
    return a;
}
__device__ __forceinline__ void sts32(uint32_t a, uint32_t v) {
    asm volatile("st.shared.b32 [%0], %1;" :: "r"(a), "r"(v) : "memory");
}
__device__ __forceinline__ void lds128(uint32_t a, uint32_t* r) {
    asm volatile("ld.shared.v4.b32 {%0,%1,%2,%3}, [%4];"
                 : "=r"(r[0]), "=r"(r[1]), "=r"(r[2]), "=r"(r[3]) : "r"(a));
}
__device__ __forceinline__ void mma8(float* d, const uint32_t* a, uint32_t b0, uint32_t b1) {
    asm volatile(
        "mma.sync.aligned.m16n8k8.row.col.f32.tf32.tf32.f32 "
        "{%0,%1,%2,%3}, {%4,%5,%6,%7}, {%8,%9}, {%0,%1,%2,%3};"
        : "+f"(d[0]), "+f"(d[1]), "+f"(d[2]), "+f"(d[3])
        : "r"(a[0]), "r"(a[1]), "r"(a[2]), "r"(a[3]), "r"(b0), "r"(b1));
}
__device__ __forceinline__ void cp16(uint32_t saddr, const void* gaddr) {
    asm volatile("cp.async.cg.shared.global [%0], [%1], 16;"
                 :: "r"(saddr), "l"(gaddr) : "memory");
}
#define CP_COMMIT() asm volatile("cp.async.commit_group;" ::: "memory")
#define CP_WAIT1()  asm volatile("cp.async.wait_group 1;" ::: "memory")

// fragment offsets within one 16KB slab image
__device__ __forceinline__ uint32_t fr_off(int ks, int f, int slot) {
    return (uint32_t)(((ks * 8 + f) * 32 + slot) << 4);
}

// ======================= prep A: x|embed|batches -> tf32 fragment image =======================
// All global loads issued up front (MLP ~12), then convert+scatter, then copy out.
__global__ void __launch_bounds__(256)
prep_a(const float* __restrict__ x, const uint32_t* __restrict__ mask,
       const float* __restrict__ embed, const float* __restrict__ batches,
       const float* __restrict__ mean)
{
    __shared__ uint32_t sf[4096];
    const int s  = blockIdx.x;
    const int rt = blockIdx.y;
    const int b  = blockIdx.z;
    const int rB = rt * 128;
    const int t  = threadIdx.x;
    const uint32_t base = smem_u32(sf);
    const int k0 = s * 32;

    if (s < 125) {                       // x region: batch all 12 LDG128 first
        float4 xv[4]; uint4 mv[4]; float4 mu[4];
#pragma unroll
        for (int p = 0; p < 4; p++) {
            const int idx = p * 256 + t;
            const int row = idx >> 3, q = idx & 7;
            const size_t gx = (size_t)(rB + row) * (NB * DIN) + (size_t)b * DIN + k0 + q * 4;
            xv[p] = *reinterpret_cast<const float4*>(x + gx);
            mv[p] = *reinterpret_cast<const uint4*>(mask + gx);
            mu[p] = *reinterpret_cast<const float4*>(mean + b * DIN + k0 + q * 4);
        }
#pragma unroll
        for (int p = 0; p < 4; p++) {
            const int idx = p * 256 + t;
            const int row = idx >> 3, q = idx & 7;
            uint32_t v[4];
            v[0] = mv[p].x ? tf32r(xv[p].x - mu[p].x) : 0u;
            v[1] = mv[p].y ? tf32r(xv[p].y - mu[p].y) : 0u;
            v[2] = mv[p].z ? tf32r(xv[p].z - mu[p].z) : 0u;
            v[3] = mv[p].w ? tf32r(xv[p].w - mu[p].w) : 0u;
            const int ks = q >> 1, mf = row >> 4, rin = row & 15;
            const int g = rin & 7, reg = (rin >> 3) + 2 * (q & 1);
#pragma unroll
            for (int i = 0; i < 4; i++)
                sts32(base + fr_off(ks, mf, (g * 4 + i) ^ ks) + reg * 4, v[i]);
        }
    } else if (s < 129) {                // embed region: batch 4 LDG128
        float4 ev[4];
#pragma unroll
        for (int p = 0; p < 4; p++) {
            const int idx = p * 256 + t;
            const int row = idx >> 3, q = idx & 7;
            ev[p] = *reinterpret_cast<const float4*>(
                embed + (size_t)(rB + row) * (NB * DE) + b * DE + (k0 - DIN) + q * 4);
        }
#pragma unroll
        for (int p = 0; p < 4; p++) {
            const int idx = p * 256 + t;
            const int row = idx >> 3, q = idx & 7;
            const uint32_t v[4] = {tf32r(ev[p].x), tf32r(ev[p].y),
                                   tf32r(ev[p].z), tf32r(ev[p].w)};
            const int ks = q >> 1, mf = row >> 4, rin = row & 15;
            const int g = rin & 7, reg = (rin >> 3) + 2 * (q & 1);
#pragma unroll
            for (int i = 0; i < 4; i++)
                sts32(base + fr_off(ks, mf, (g * 4 + i) ^ ks) + reg * 4, v[i]);
        }
    } else {                             // batches tail: zero-pad, then ks=0 frags
        const float4 bv = *reinterpret_cast<const float4*>(
            batches + (size_t)(rB + (t >> 1)) * DB + (t & 1) * 4);
        for (int i = t; i < 4096; i += 256) sf[i] = 0;
        __syncthreads();
        const int row = t >> 1, q = t & 1;
        const uint32_t v[4] = {tf32r(bv.x), tf32r(bv.y), tf32r(bv.z), tf32r(bv.w)};
        const int mf = row >> 4, rin = row & 15;
        const int g = rin & 7, reg = (rin >> 3) + 2 * q;
#pragma unroll
        for (int i = 0; i < 4; i++)
            sts32(base + fr_off(0, mf, g * 4 + i) + reg * 4, v[i]);
    }
    __syncthreads();

    uint4* dst = reinterpret_cast<uint4*>(
        g_Afrag + ((size_t)(b * 32 + rt) * NSLAB + s) * SLAB_BYTES);
    const uint4* src = reinterpret_cast<const uint4*>(sf);
#pragma unroll
    for (int i = 0; i < 4; i++) dst[i * 256 + t] = src[i * 256 + t];
}

// ======================= prep W: W -> tf32 fragment image =======================
__global__ void __launch_bounds__(256)
prep_w(const float* __restrict__ W)
{
    __shared__ uint32_t sf[4096];
    const int s   = blockIdx.x;
    const int cbi = blockIdx.y;
    const int b   = blockIdx.z;
    const int t   = threadIdx.x;
    const uint32_t base = smem_u32(sf);
    const int k0 = s * 32;
    const float* Wb = W + (size_t)b * KD * MD + cbi * 128;

    if (s < 129) {                        // batch 4 LDG128 first
        float4 wv[4];
#pragma unroll
        for (int p = 0; p < 4; p++) {
            const int idx = p * 256 + t;
            const int krow = idx >> 5, n0 = (idx & 31) * 4;
            wv[p] = *reinterpret_cast<const float4*>(Wb + (size_t)(k0 + krow) * MD + n0);
        }
#pragma unroll
        for (int p = 0; p < 4; p++) {
            const int idx = p * 256 + t;
            const int krow = idx >> 5, n0 = (idx & 31) * 4;
            const uint32_t v[4] = {tf32r(wv[p].x), tf32r(wv[p].y),
                                   tf32r(wv[p].z), tf32r(wv[p].w)};
            const int ks = krow >> 3, tk = krow & 3, kh = (krow >> 2) & 1;
#pragma unroll
            for (int i = 0; i < 4; i++) {
                const int n = n0 + i, g = n & 7, nf = n >> 3, np = nf >> 1;
                const int reg = (nf & 1) * 2 + kh;
                sts32(base + fr_off(ks, np, (g * 4 + tk) ^ np) + reg * 4, v[i]);
            }
        }
    } else {                              // tail: zero-pad + 8 k-rows (ks=0)
        const int krow = t >> 5, n0 = (t & 31) * 4;
        const float4 wv4 = *reinterpret_cast<const float4*>(
            Wb + (size_t)(k0 + krow) * MD + n0);
        for (int i = t; i < 4096; i += 256) sf[i] = 0;
        __syncthreads();
        const uint32_t v[4] = {tf32r(wv4.x), tf32r(wv4.y), tf32r(wv4.z), tf32r(wv4.w)};
        const int tk = krow & 3, kh = (krow >> 2) & 1;
#pragma unroll
        for (int i = 0; i < 4; i++) {
            const int n = n0 + i, g = n & 7, nf = n >> 3, np = nf >> 1;
            const int reg = (nf & 1) * 2 + kh;
            sts32(base + fr_off(0, np, (g * 4 + tk) ^ np) + reg * 4, v[i]);
        }
    }
    __syncthreads();

    uint4* dst = reinterpret_cast<uint4*>(
        g_Wfrag + ((size_t)(b * 4 + cbi) * NSLAB + s) * SLAB_BYTES);
    const uint4* src = reinterpret_cast<const uint4*>(sf);
#pragma unroll
    for (int i = 0; i < 4; i++) dst[i * 256 + t] = src[i * 256 + t];
}

// ======================= main: cp.async pipeline + HMMA =======================
__global__ void __launch_bounds__(256, 2)
ib_main(const float* __restrict__ bias, float* __restrict__ out)
{
    extern __shared__ char smem[];
    const uint32_t sb = smem_u32(smem);
    const int t    = threadIdx.x;
    const int lane = t & 31;
    const int wid  = t >> 5;
    const int wm   = wid & 3;
    const int wn   = wid >> 2;
    const int cbi  = blockIdx.x;
    const int rt   = blockIdx.y;
    const int b    = blockIdx.z;
    const int rB   = rt * 128;
    const int cB   = cbi * 128;

    const uint8_t* gA = g_Afrag + (size_t)(b * 32 + rt) * NSLAB * SLAB_BYTES;
    const uint8_t* gW = g_Wfrag + (size_t)(b * 4 + cbi) * NSLAB * SLAB_BYTES;

    float acc[2][8][4];
#pragma unroll
    for (int m = 0; m < 2; m++)
#pragma unroll
        for (int n = 0; n < 8; n++)
#pragma unroll
            for (int q = 0; q < 4; q++) acc[m][n][q] = 0.f;

    auto cp_slab = [&](int s) {
        const uint32_t buf = sb + (uint32_t)((s % 3) * BUF_BYTES);
        const uint8_t* as = gA + (size_t)s * SLAB_BYTES;
        const uint8_t* ws = gW + (size_t)s * SLAB_BYTES;
#pragma unroll
        for (int i = 0; i < 4; i++) {
            const uint32_t off = (uint32_t)(i * 256 + t) * 16;
            cp16(buf + off, as + off);
            cp16(buf + SLAB_BYTES + off, ws + off);
        }
    };

    auto consume = [&](uint32_t buf, int ks) {
        uint32_t afr[2][4], bfr[4][4];
#pragma unroll
        for (int m = 0; m < 2; m++)
            lds128(buf + fr_off(ks, wm * 2 + m, lane ^ ks), afr[m]);
#pragma unroll
        for (int pp = 0; pp < 4; pp++) {
            const int np = wn * 4 + pp;
            lds128(buf + SLAB_BYTES + fr_off(ks, np, lane ^ np), bfr[pp]);
        }
#pragma unroll
        for (int m = 0; m < 2; m++)
#pragma unroll
            for (int pp = 0; pp < 4; pp++) {
                mma8(acc[m][2 * pp],     afr[m], bfr[pp][0], bfr[pp][1]);
                mma8(acc[m][2 * pp + 1], afr[m], bfr[pp][2], bfr[pp][3]);
            }
    };

    // prologue: prefetch slabs 0,1
    cp_slab(0); CP_COMMIT();
    cp_slab(1); CP_COMMIT();

    for (int s = 0; s < NSLAB; s++) {
        CP_WAIT1();               // slab s arrived (<=1 newer group pending)
        __syncthreads();          // all warps done with slab s-1, data visible
        if (s + 2 < NSLAB) cp_slab(s + 2);
        CP_COMMIT();              // exactly one group per iteration
        const uint32_t buf = sb + (uint32_t)((s % 3) * BUF_BYTES);
        consume(buf, 0);
        consume(buf, 1);
        consume(buf, 2);
        consume(buf, 3);
    }

    // -------- epilogue: bias + LeakyReLU --------
    const int g  = lane >> 2;
    const int tq = lane & 3;
#pragma unroll
    for (int m = 0; m < 2; m++) {
        const int r0 = rB + wm * 32 + m * 16 + g;
#pragma unroll
        for (int nf = 0; nf < 8; nf++) {
            const int col = cB + wn * 64 + nf * 8 + tq * 2;
            const float2 bv = *reinterpret_cast<const float2*>(bias + b * MD + col);
            float v0 = acc[m][nf][0] + bv.x;
            float v1 = acc[m][nf][1] + bv.y;
            float v2 = acc[m][nf][2] + bv.x;
            float v3 = acc[m][nf][3] + bv.y;
            v0 = (v0 >= 0.f) ? v0 : ALPHA * v0;
            v1 = (v1 >= 0.f) ? v1 : ALPHA * v1;
            v2 = (v2 >= 0.f) ? v2 : ALPHA * v2;
            v3 = (v3 >= 0.f) ? v3 : ALPHA * v3;
            *reinterpret_cast<float2*>(out + (size_t)r0 * (NB * MD) + b * MD + col)
                = make_float2(v0, v1);
            *reinterpret_cast<float2*>(out + (size_t)(r0 + 8) * (NB * MD) + b * MD + col)
                = make_float2(v2, v3);
        }
    }
}

} // namespace

extern "C" void kernel_launch(void* const* d_in, const int* in_sizes, int n_in,
                              void* d_out, int out_size)
{
    const float*    x       = (const float*)d_in[0];
    const uint32_t* mask    = (const uint32_t*)d_in[1];
    const float*    embed   = (const float*)d_in[2];
    const float*    batches = (const float*)d_in[3];
    const float*    mean    = (const float*)d_in[4];
    const float*    W       = (const float*)d_in[5];
    const float*    bias    = (const float*)d_in[6];
    float*          out     = (float*)d_out;

    prep_w<<<dim3(NSLAB, 4, NB), 256>>>(W);
    prep_a<<<dim3(NSLAB, 32, NB), 256>>>(x, mask, embed, batches, mean);

    cudaFuncSetAttribute(ib_main, cudaFuncAttributeMaxDynamicSharedMemorySize, SMEM_MAIN);
    ib_main<<<dim3(4, 32, NB), 256, SMEM_MAIN>>>(bias, out);
}